// round 14
// baseline (speedup 1.0000x reference)
#include <cuda_runtime.h>
#include <math.h>
#include <stdint.h>

// MemoryUnit, Round 13: 2-CTA cluster per batch element, 512 threads/CTA.
// vs R12: slot-GEMM rebalanced A/B by i-rows (A: [0,96) contiguous, B:
// [96,256)) with producer/consumer named barrier (A arrives after publishing
// partials, B syncs before combining). A runs the serial chain after its GEMM
// share. Critical-warp FFMA 4.6K -> 3.3K. 2 cluster syncs/step unchanged.

namespace {
constexpr int S_ = 2048;
constexpr int B_ = 64;
constexpr int D_ = 256;
constexpr int K_ = 16;
constexpr int NT = 512;
constexpr int NSPLIT = 96;            // A's share of slot-GEMM i-rows
constexpr float EPSLN = 1e-5f;
constexpr float MOMC  = 0.9f;

__device__ __forceinline__ float geluf(float v) {
    return 0.5f * v * (1.0f + erff(v * 0.70710678118654752440f));
}
__device__ __forceinline__ float sigmf(float v) {
    return 1.0f / (1.0f + expf(-v));
}
__device__ __forceinline__ uint32_t smem_u32(const void* p) {
    return (uint32_t)__cvta_generic_to_shared(const_cast<void*>(p));
}
__device__ __forceinline__ uint32_t peer_addr(uint32_t la, uint32_t peer) {
    uint32_t ra;
    asm("mapa.shared::cluster.u32 %0, %1, %2;" : "=r"(ra) : "r"(la), "r"(peer));
    return ra;
}
__device__ __forceinline__ void st_peer_f32(uint32_t ra, float v) {
    asm volatile("st.shared::cluster.f32 [%0], %1;" :: "r"(ra), "f"(v) : "memory");
}
__device__ __forceinline__ void st_peer_f128(uint32_t ra, float4 v) {
    asm volatile("st.shared::cluster.v4.f32 [%0], {%1,%2,%3,%4};"
                 :: "r"(ra), "f"(v.x), "f"(v.y), "f"(v.z), "f"(v.w) : "memory");
}
__device__ __forceinline__ void cluster_sync_() {
    asm volatile("barrier.cluster.arrive.aligned;\n\t"
                 "barrier.cluster.wait.aligned;" ::: "memory");
}
__device__ __forceinline__ void barA() { asm volatile("bar.sync 1, 256;" ::: "memory"); }
__device__ __forceinline__ void barP_arrive() {   // producer: non-blocking
    asm volatile("bar.arrive 3, 512;" ::: "memory");
}
__device__ __forceinline__ void barP_sync() {     // consumer: blocks for producers
    asm volatile("bar.sync 3, 512;" ::: "memory");
}
} // namespace

__global__ __launch_bounds__(NT, 1) __cluster_dims__(2, 1, 1)
void memunit_kernel(
    const float* __restrict__ x,     const float* __restrict__ slot_init,
    const float* __restrict__ Wq,    const float* __restrict__ bq,
    const float* __restrict__ Wk,    const float* __restrict__ bk,
    const float* __restrict__ Wv,    const float* __restrict__ bv,
    const float* __restrict__ wg1W,  const float* __restrict__ wg1b,
    const float* __restrict__ wg2W,  const float* __restrict__ wg2b,
    const float* __restrict__ egW,   const float* __restrict__ egb,
    const float* __restrict__ wcW,   const float* __restrict__ wcb,
    const float* __restrict__ wclng, const float* __restrict__ wclnb,
    const float* __restrict__ fuW,   const float* __restrict__ fub,
    const float* __restrict__ fulng, const float* __restrict__ fulnb,
    const float* __restrict__ ong,   const float* __restrict__ onb,
    float* __restrict__ out)
{
    __shared__ float sM[D_][K_];       // full M, feature-major, peer-mirrored
    __shared__ float scat[2 * D_];     // [x_t | r], fully local
    __shared__ float sQ[D_];           // full q (with bias), local
    __shared__ float sKv[D_];          // Wk @ q, local
    __shared__ float sMbar[D_];        // attn-weighted slot average, local
    __shared__ float sAP[256][17];     // A's slot-GEMM partials (16 slots + aux)
    __shared__ float sG[128][K_];      // gelu(write pre-act), local-o rows
    __shared__ float sE[128][K_];      // sigmoid(erase pre-act)
    __shared__ float sLP[8][K_];       // logit warp partials
    __shared__ float sGP[4][2 * K_];   // wc-warp gstat partials
    __shared__ float sGloc[2 * K_], eG[2 * K_];
    __shared__ float sFBf[128], sFBg[128]; // B's fu-hi / wg1-hi partials per o
    __shared__ float sBRf[4][2];       // fu-LN warp partials (A warps 0-3)
    __shared__ float sBRg[4];          // wg2 warp partials (A warps 4-7)
    __shared__ float sUW[4][2];        // out-LN warp partials
    __shared__ float sF[3], eF[3], sU[2], eU[2];
    __shared__ float sAttn[K_], sEvict[K_], sPers[K_], sMean[K_], sRstd[K_];
    __shared__ float sNov;

    const int tid  = threadIdx.x;
    const int lane = tid & 31;
    const int wid  = tid >> 5;
    const bool isA = tid < 256;
    const int gt   = tid & 255;        // group-local id
    const int o    = gt & 127;         // half-width output feature
    const int hb   = gt >> 7;          // matrix select: 0=eg, 1=wc (both groups)
    uint32_t rank;
    asm("mov.u32 %0, %%cluster_ctarank;" : "=r"(rank));
    const uint32_t peer = rank ^ 1u;
    const int b  = blockIdx.x >> 1;
    const int og = (int)rank * 128 + o;   // this CTA's output column

    if (tid < D_) {
        #pragma unroll
        for (int j = 0; j < K_; ++j) sM[tid][j] = slot_init[j * D_ + tid];
    }
    if (tid < K_) sPers[tid] = 0.f;

    const float wg2b0 = wg2b[0];
    float bqF = 0.f, bvF = 0.f;        // A full-width constants (o = gt)
    float cA2 = 0.f, cA3 = 0.f, cA4 = 0.f, ongo = 0.f, onbo = 0.f;
    if (isA) {
        bqF = bq[gt]; bvF = bv[gt];
        if (hb == 0) {
            cA2 = fub[og]; cA3 = fulng[og]; cA4 = fulnb[og];
            ongo = ong[og]; onbo = onb[og];
        } else {
            cA2 = wg1b[og]; cA3 = wg2W[og];
        }
    }
    const float cbM = hb ? wcb[og] : egb[og];   // B epilogue bias
    const int  urow = gt >> 1;                  // B M-update row (local)
    const int  grow = (int)rank * 128 + urow;
    float cgU = 0.f, cbU = 0.f;
    if (!isA) { cgU = wclng[grow]; cbU = wclnb[grow]; }
    const float* Wm = hb ? wcW : egW;           // slot-GEMM matrix (both groups)
    const float* Wf = hb ? wg1W : fuW;          // fu/wg1 matrix per role
    __syncthreads();

    for (int t = 0; t < S_; ++t) {
        if (tid < D_) scat[tid] = x[((size_t)t * B_ + b) * D_ + tid];
        __syncthreads();   // S0

        // slot-GEMM accumulators (both groups; A's share is rows [0,NSPLIT))
        float acc[K_];
        float aux = 0.f;
        #pragma unroll
        for (int j = 0; j < K_; ++j) acc[j] = 0.f;

        auto chunk = [&](int c0, int c1) {
            for (int c = c0; c < c1; c += 4) {
                float wa[4], ws[4];
                #pragma unroll
                for (int u = 0; u < 4; ++u) {
                    wa[u] = Wm[(c + u) * D_ + og];          // x-part row
                    ws[u] = Wm[(D_ + c + u) * D_ + og];     // slot-part row
                }
                #pragma unroll
                for (int u = 0; u < 4; ++u) {
                    const int i = c + u;
                    aux = fmaf(scat[i], wa[u], aux);
                    const float4* mr = reinterpret_cast<const float4*>(sM[i]);
                    const float4 m0 = mr[0], m1 = mr[1], m2 = mr[2], m3 = mr[3];
                    const float mv[K_] = {m0.x,m0.y,m0.z,m0.w, m1.x,m1.y,m1.z,m1.w,
                                          m2.x,m2.y,m2.z,m2.w, m3.x,m3.y,m3.z,m3.w};
                    #pragma unroll
                    for (int j = 0; j < K_; ++j)
                        acc[j] = fmaf(mv[j], ws[u], acc[j]);
                }
            }
        };

        if (isA) {
            // ---- A's GEMM share, publish, signal ----
            chunk(0, NSPLIT);
            #pragma unroll
            for (int j = 0; j < K_; ++j) sAP[gt][j] = acc[j];
            sAP[gt][16] = aux;
            barP_arrive();   // non-blocking handoff to B

            // ---- serial chain (unchanged from R12) ----
            float q = 0.f;
            for (int c = 0; c < D_; c += 8) {
                float w[8];
                #pragma unroll
                for (int u = 0; u < 8; ++u) w[u] = Wq[(c + u) * D_ + gt];
                #pragma unroll
                for (int u = 0; u < 8; ++u) q = fmaf(scat[c + u], w[u], q);
            }
            sQ[gt] = q + bqF;
            barA();
            const float4 q4lo = reinterpret_cast<const float4*>(sQ)[lane];
            const float4 q4hi = reinterpret_cast<const float4*>(sQ)[lane + 32];
            for (int r = wid; r < D_; r += 8) {
                const float* wr = Wk + (size_t)r * D_;
                const float4 wlo = reinterpret_cast<const float4*>(wr)[lane];
                const float4 whi = reinterpret_cast<const float4*>(wr)[lane + 32];
                float a = wlo.x * q4lo.x;
                a = fmaf(wlo.y, q4lo.y, a);
                a = fmaf(wlo.z, q4lo.z, a);
                a = fmaf(wlo.w, q4lo.w, a);
                a = fmaf(whi.x, q4hi.x, a);
                a = fmaf(whi.y, q4hi.y, a);
                a = fmaf(whi.z, q4hi.z, a);
                a = fmaf(whi.w, q4hi.w, a);
                #pragma unroll
                for (int off = 16; off; off >>= 1)
                    a += __shfl_xor_sync(0xffffffffu, a, off);
                if (lane == 0) sKv[r] = a;
            }
            barA();
            {
                const float kv = sKv[gt];
                const float4* mr = reinterpret_cast<const float4*>(sM[gt]);
                const float4 m0 = mr[0], m1 = mr[1], m2 = mr[2], m3 = mr[3];
                const float mv[K_] = {m0.x,m0.y,m0.z,m0.w, m1.x,m1.y,m1.z,m1.w,
                                      m2.x,m2.y,m2.z,m2.w, m3.x,m3.y,m3.z,m3.w};
                float p[K_];
                #pragma unroll
                for (int j = 0; j < K_; ++j) p[j] = mv[j] * kv;
                #pragma unroll
                for (int off = 1; off < 32; off <<= 1) {
                    #pragma unroll
                    for (int j = 0; j < K_; ++j)
                        p[j] += __shfl_xor_sync(0xffffffffu, p[j], off);
                }
                if (lane == 0) {
                    #pragma unroll
                    for (int j = 0; j < K_; ++j) sLP[wid][j] = p[j];
                }
            }
            barA();
            if (tid < K_) {
                float l = 0.f;
                #pragma unroll
                for (int w = 0; w < 8; ++w) l += sLP[w][tid];
                l *= 0.0625f;
                float mx = l;
                #pragma unroll
                for (int off = 8; off; off >>= 1) mx = fmaxf(mx, __shfl_xor_sync(0xffffu, mx, off, 16));
                const float e = expf(l - mx);
                float s = e;
                #pragma unroll
                for (int off = 8; off; off >>= 1) s += __shfl_xor_sync(0xffffu, s, off, 16);
                const float a = e / s;
                sAttn[tid] = a;
                if (tid == 0) sNov = 1.f - 1.f / s;
                const float pr = MOMC * sPers[tid] + (1.f - MOMC) * a;
                sPers[tid] = pr;
                float el = -4.f * pr, em = el;
                #pragma unroll
                for (int off = 8; off; off >>= 1) em = fmaxf(em, __shfl_xor_sync(0xffffu, em, off, 16));
                const float ee = expf(el - em);
                float es = ee;
                #pragma unroll
                for (int off = 8; off; off >>= 1) es += __shfl_xor_sync(0xffffu, es, off, 16);
                sEvict[tid] = ee / es;
            }
            barA();
            {
                const float4* mr = reinterpret_cast<const float4*>(sM[gt]);
                const float4 m0 = mr[0], m1 = mr[1], m2 = mr[2], m3 = mr[3];
                const float mv[K_] = {m0.x,m0.y,m0.z,m0.w, m1.x,m1.y,m1.z,m1.w,
                                      m2.x,m2.y,m2.z,m2.w, m3.x,m3.y,m3.z,m3.w};
                float a = 0.f;
                #pragma unroll
                for (int j = 0; j < K_; ++j) a = fmaf(sAttn[j], mv[j], a);
                sMbar[gt] = a;
            }
            barA();
            float r = 0.f;
            for (int c = 0; c < D_; c += 8) {
                float w[8];
                #pragma unroll
                for (int u = 0; u < 8; ++u) w[u] = Wv[(c + u) * D_ + gt];
                #pragma unroll
                for (int u = 0; u < 8; ++u) r = fmaf(sMbar[c + u], w[u], r);
            }
            scat[D_ + gt] = r + bvF;
        } else {
            // ---- B: its GEMM share, then consume A's partials ----
            chunk(NSPLIT, D_);
            barP_sync();     // wait for A's sAP publish
            #pragma unroll
            for (int j = 0; j < K_; ++j) acc[j] += sAP[gt][j];
            aux += sAP[gt][16];
            if (hb == 0) {   // erase epilogue (warps 8-11)
                float e[K_];
                #pragma unroll
                for (int j = 0; j < K_; ++j) e[j] = sigmf(acc[j] + aux + cbM);
                float4* er = reinterpret_cast<float4*>(sE[o]);
                er[0] = make_float4(e[0],  e[1],  e[2],  e[3]);
                er[1] = make_float4(e[4],  e[5],  e[6],  e[7]);
                er[2] = make_float4(e[8],  e[9],  e[10], e[11]);
                er[3] = make_float4(e[12], e[13], e[14], e[15]);
            } else {         // write-candidate epilogue + gstats (warps 12-15)
                float g[K_], gs[K_], gq[K_];
                #pragma unroll
                for (int j = 0; j < K_; ++j) {
                    g[j]  = geluf(acc[j] + aux + cbM);
                    gs[j] = g[j];
                    gq[j] = g[j] * g[j];
                }
                #pragma unroll
                for (int off = 1; off < 32; off <<= 1) {
                    #pragma unroll
                    for (int j = 0; j < K_; ++j) {
                        gs[j] += __shfl_xor_sync(0xffffffffu, gs[j], off);
                        gq[j] += __shfl_xor_sync(0xffffffffu, gq[j], off);
                    }
                }
                if (lane == 0) {
                    #pragma unroll
                    for (int j = 0; j < K_; ++j) {
                        sGP[wid - 12][j]      = gs[j];
                        sGP[wid - 12][K_ + j] = gq[j];
                    }
                }
                float4* gr = reinterpret_cast<float4*>(sG[o]);
                gr[0] = make_float4(g[0],  g[1],  g[2],  g[3]);
                gr[1] = make_float4(g[4],  g[5],  g[6],  g[7]);
                gr[2] = make_float4(g[8],  g[9],  g[10], g[11]);
                gr[3] = make_float4(g[12], g[13], g[14], g[15]);
            }
        }
        __syncthreads();   // S1: r + sG/sE/sGP ready; A done reading sM

        // ---- fu / wg1 quadrants: A = cat[0..255], B = cat[256..511] ----
        float accf = 0.f;
        {
            const int base = isA ? 0 : 256;
            for (int c = 0; c < 256; c += 8) {
                float w[8];
                #pragma unroll
                for (int u = 0; u < 8; ++u) w[u] = Wf[(base + c + u) * D_ + og];
                #pragma unroll
                for (int u = 0; u < 8; ++u) accf = fmaf(scat[base + c + u], w[u], accf);
            }
        }
        if (!isA) { if (hb == 0) sFBf[o] = accf; else sFBg[o] = accf; }
        __syncthreads();   // S2

        float hf = 0.f;
        if (isA) {
            if (hb == 0) {
                hf = geluf(accf + sFBf[o] + cA2);
                float b0 = hf, b1 = hf * hf;
                #pragma unroll
                for (int off = 1; off < 32; off <<= 1) {
                    b0 += __shfl_xor_sync(0xffffffffu, b0, off);
                    b1 += __shfl_xor_sync(0xffffffffu, b1, off);
                }
                if (lane == 0) { sBRf[wid][0] = b0; sBRf[wid][1] = b1; }
            } else {
                const float hg = geluf(accf + sFBg[o] + cA2);
                float a2 = hg * cA3;
                #pragma unroll
                for (int off = 1; off < 32; off <<= 1)
                    a2 += __shfl_xor_sync(0xffffffffu, a2, off);
                if (lane == 0) sBRg[wid - 4] = a2;
            }
            barA();
            if (tid < 3) {
                float s;
                if (tid < 2) s = sBRf[0][tid] + sBRf[1][tid] + sBRf[2][tid] + sBRf[3][tid];
                else         s = sBRg[0] + sBRg[1] + sBRg[2] + sBRg[3];
                sF[tid] = s;
                st_peer_f32(peer_addr(smem_u32(&eF[tid]), peer), s);
            }
        } else if (gt < 2 * K_) {
            const float s = sGP[0][gt] + sGP[1][gt] + sGP[2][gt] + sGP[3][gt];
            sGloc[gt] = s;
            st_peer_f32(peer_addr(smem_u32(&eG[gt]), peer), s);
        }
        cluster_sync_();   // C1: eF + eG exchanged

        const float gw = sigmf(sF[2] + eF[2] + wg2b0) * sNov;
        if (tid < K_) {
            sPers[tid] += sEvict[tid] * gw * 0.1f;
            const float gsum = sGloc[tid] + eG[tid];
            const float gsq  = sGloc[K_ + tid] + eG[K_ + tid];
            const float mean = gsum * (1.f / D_);
            const float var  = gsq * (1.f / D_) - mean * mean;
            sMean[tid] = mean;
            sRstd[tid] = rsqrtf(var + EPSLN);
        }
        __syncthreads();   // S3: mean/rstd visible

        float uu = 0.f;
        if (isA) {
            if (hb == 0) {
                const float fsum = sF[0] + eF[0], fsq = sF[1] + eF[1];
                const float fmn = fsum * (1.f / D_);
                const float fvr = fsq * (1.f / D_) - fmn * fmn;
                const float frs = rsqrtf(fvr + EPSLN);
                const float outt = (hf - fmn) * frs * cA3 + cA4;
                uu = outt + scat[og];
                float b0 = uu, b1 = uu * uu;
                #pragma unroll
                for (int off = 1; off < 32; off <<= 1) {
                    b0 += __shfl_xor_sync(0xffffffffu, b0, off);
                    b1 += __shfl_xor_sync(0xffffffffu, b1, off);
                }
                if (lane == 0) { sUW[wid][0] = b0; sUW[wid][1] = b1; }
            }
            barA();
            if (tid < 2) {
                const float s = sUW[0][tid] + sUW[1][tid] + sUW[2][tid] + sUW[3][tid];
                sU[tid] = s;
                st_peer_f32(peer_addr(smem_u32(&eU[tid]), peer), s);
            }
        } else {
            const int colb = (gt & 1) * 8;
            float nm[8];
            #pragma unroll
            for (int c = 0; c < 8; ++c) {
                const int j = colb + c;
                const float al = gw * sEvict[j];
                const float wr = (sG[urow][j] - sMean[j]) * sRstd[j] * cgU + cbU;
                nm[c] = sM[grow][j] * (1.f - al * sE[urow][j]) + al * wr;
            }
            float4* rowp = reinterpret_cast<float4*>(&sM[grow][colb]);
            rowp[0] = make_float4(nm[0], nm[1], nm[2], nm[3]);
            rowp[1] = make_float4(nm[4], nm[5], nm[6], nm[7]);
            uint32_t ra = peer_addr(smem_u32(&sM[grow][colb]), peer);
            st_peer_f128(ra,      make_float4(nm[0], nm[1], nm[2], nm[3]));
            st_peer_f128(ra + 16, make_float4(nm[4], nm[5], nm[6], nm[7]));
        }
        cluster_sync_();   // C2: eU + peer M halves visible

        if (isA && hb == 0) {
            const float usum = sU[0] + eU[0], usq = sU[1] + eU[1];
            const float um = usum * (1.f / D_);
            const float uv = usq * (1.f / D_) - um * um;
            const float rr = rsqrtf(uv + EPSLN);
            out[((size_t)t * B_ + b) * D_ + og] = (uu - um) * rr * ongo + onbo;
        }
    }

    // proto = transpose(M, (1,0,2)) : [K, B, d]
    if (isA && hb == 0) {
        #pragma unroll
        for (int j = 0; j < K_; ++j)
            out[(size_t)S_ * B_ * D_ + ((size_t)j * B_ + b) * D_ + og] = sM[og][j];
    }
}

extern "C" void kernel_launch(void* const* d_in, const int* in_sizes, int n_in,
                              void* d_out, int out_size) {
    (void)in_sizes; (void)n_in; (void)out_size;
    memunit_kernel<<<2 * B_, NT>>>(
        (const float*)d_in[0],  (const float*)d_in[1],
        (const float*)d_in[2],  (const float*)d_in[3],
        (const float*)d_in[4],  (const float*)d_in[5],
        (const float*)d_in[6],  (const float*)d_in[7],
        (const float*)d_in[8],  (const float*)d_in[9],
        (const float*)d_in[10], (const float*)d_in[11],
        (const float*)d_in[12], (const float*)d_in[13],
        (const float*)d_in[14], (const float*)d_in[15],
        (const float*)d_in[16], (const float*)d_in[17],
        (const float*)d_in[18], (const float*)d_in[19],
        (const float*)d_in[20], (const float*)d_in[21],
        (const float*)d_in[22], (const float*)d_in[23],
        (float*)d_out);
}

// round 15
// speedup vs baseline: 1.1239x; 1.1239x over previous
#include <cuda_runtime.h>
#include <math.h>
#include <stdint.h>

// MemoryUnit, Round 14: R12 structure (best: 55.8ms) + packed-transposed
// weights. Prepass repacks o-indexed matrices into T[i/4][o] = float4 of 4
// consecutive-i values -> main-kernel weight loops use 1 LDG.128 per 4 i
// (4x fewer LDG issues + addressing), same bytes/wavefronts.

namespace {
constexpr int S_ = 2048;
constexpr int B_ = 64;
constexpr int D_ = 256;
constexpr int K_ = 16;
constexpr int NT = 512;
constexpr float EPSLN = 1e-5f;
constexpr float MOMC  = 0.9f;

__device__ __forceinline__ float geluf(float v) {
    return 0.5f * v * (1.0f + erff(v * 0.70710678118654752440f));
}
__device__ __forceinline__ float sigmf(float v) {
    return 1.0f / (1.0f + expf(-v));
}
__device__ __forceinline__ uint32_t smem_u32(const void* p) {
    return (uint32_t)__cvta_generic_to_shared(const_cast<void*>(p));
}
__device__ __forceinline__ uint32_t peer_addr(uint32_t la, uint32_t peer) {
    uint32_t ra;
    asm("mapa.shared::cluster.u32 %0, %1, %2;" : "=r"(ra) : "r"(la), "r"(peer));
    return ra;
}
__device__ __forceinline__ void st_peer_f32(uint32_t ra, float v) {
    asm volatile("st.shared::cluster.f32 [%0], %1;" :: "r"(ra), "f"(v) : "memory");
}
__device__ __forceinline__ void st_peer_f128(uint32_t ra, float4 v) {
    asm volatile("st.shared::cluster.v4.f32 [%0], {%1,%2,%3,%4};"
                 :: "r"(ra), "f"(v.x), "f"(v.y), "f"(v.z), "f"(v.w) : "memory");
}
__device__ __forceinline__ void cluster_sync_() {
    asm volatile("barrier.cluster.arrive.aligned;\n\t"
                 "barrier.cluster.wait.aligned;" ::: "memory");
}
__device__ __forceinline__ void barA() { asm volatile("bar.sync 1, 256;" ::: "memory"); }
} // namespace

// Packed weight scratch: T[i>>2][o] = {W[i][o], W[i+1][o], W[i+2][o], W[i+3][o]}
__device__ float4 tEgX[64 * 256];     // egW rows [0,256)
__device__ float4 tEgS[64 * 256];     // egW rows [256,512)
__device__ float4 tWcX[64 * 256];
__device__ float4 tWcS[64 * 256];
__device__ float4 tFu[128 * 256];     // fuW rows [0,512)
__device__ float4 tWg1[128 * 256];
__device__ float4 tWq[64 * 256];
__device__ float4 tWv[64 * 256];

__global__ void pack_kernel(const float* __restrict__ src, float4* __restrict__ dst) {
    // one block per i4-group (256 threads = o); src is [4*gridDim.x][256]
    const int i4 = blockIdx.x;
    const int o  = threadIdx.x;
    const float a = src[(i4 * 4 + 0) * D_ + o];
    const float b = src[(i4 * 4 + 1) * D_ + o];
    const float c = src[(i4 * 4 + 2) * D_ + o];
    const float d = src[(i4 * 4 + 3) * D_ + o];
    dst[i4 * D_ + o] = make_float4(a, b, c, d);
}

__global__ __launch_bounds__(NT, 1) __cluster_dims__(2, 1, 1)
void memunit_kernel(
    const float* __restrict__ x,     const float* __restrict__ slot_init,
    const float* __restrict__ Wk,    const float* __restrict__ bq,
    const float* __restrict__ bv,
    const float* __restrict__ wg1b,  const float* __restrict__ wg2W,
    const float* __restrict__ wg2b,
    const float* __restrict__ egb,   const float* __restrict__ wcb,
    const float* __restrict__ wclng, const float* __restrict__ wclnb,
    const float* __restrict__ fub,
    const float* __restrict__ fulng, const float* __restrict__ fulnb,
    const float* __restrict__ ong,   const float* __restrict__ onb,
    float* __restrict__ out)
{
    __shared__ float sM[D_][K_];       // full M, feature-major, peer-mirrored
    __shared__ float scat[2 * D_];     // [x_t | r], fully local
    __shared__ float sQ[D_];           // full q (with bias), local
    __shared__ float sKv[D_];          // Wk @ q, local
    __shared__ float sMbar[D_];        // attn-weighted slot average, local
    __shared__ float sG[128][K_];      // gelu(write pre-act), local-o rows
    __shared__ float sE[128][K_];      // sigmoid(erase pre-act)
    __shared__ float sLP[8][K_];       // logit warp partials
    __shared__ float sGP[4][2 * K_];   // wc-warp gstat partials
    __shared__ float sGloc[2 * K_], eG[2 * K_];
    __shared__ float sFBf[128], sFBg[128]; // B's fu-hi / wg1-hi partials per o
    __shared__ float sBRf[4][2];       // fu-LN warp partials (A warps 0-3)
    __shared__ float sBRg[4];          // wg2 warp partials (A warps 4-7)
    __shared__ float sUW[4][2];        // out-LN warp partials
    __shared__ float sF[3], eF[3], sU[2], eU[2];
    __shared__ float sAttn[K_], sEvict[K_], sPers[K_], sMean[K_], sRstd[K_];
    __shared__ float sNov;

    const int tid  = threadIdx.x;
    const int lane = tid & 31;
    const int wid  = tid >> 5;
    const bool isA = tid < 256;
    const int gt   = tid & 255;        // group-local id
    const int o    = gt & 127;         // half-width output feature
    const int hb   = gt >> 7;          // role select
    uint32_t rank;
    asm("mov.u32 %0, %%cluster_ctarank;" : "=r"(rank));
    const uint32_t peer = rank ^ 1u;
    const int b  = blockIdx.x >> 1;
    const int og = (int)rank * 128 + o;

    if (tid < D_) {
        #pragma unroll
        for (int j = 0; j < K_; ++j) sM[tid][j] = slot_init[j * D_ + tid];
    }
    if (tid < K_) sPers[tid] = 0.f;

    const float wg2b0 = wg2b[0];
    float bqF = 0.f, bvF = 0.f;
    float cA2 = 0.f, cA3 = 0.f, cA4 = 0.f, ongo = 0.f, onbo = 0.f;
    if (isA) {
        bqF = bq[gt]; bvF = bv[gt];
        if (hb == 0) {
            cA2 = fub[og]; cA3 = fulng[og]; cA4 = fulnb[og];
            ongo = ong[og]; onbo = onb[og];
        } else {
            cA2 = wg1b[og]; cA3 = wg2W[og];
        }
    }
    const float cbM = hb ? wcb[og] : egb[og];
    const int  urow = gt >> 1;
    const int  grow = (int)rank * 128 + urow;
    float cgU = 0.f, cbU = 0.f;
    if (!isA) { cgU = wclng[grow]; cbU = wclnb[grow]; }
    const float4* TmX = hb ? tWcX : tEgX;   // x-part, packed
    const float4* TmS = hb ? tWcS : tEgS;   // slot-part, packed
    const float4* Tf  = hb ? tWg1 : tFu;    // fu/wg1 per role, packed
    __syncthreads();

    for (int t = 0; t < S_; ++t) {
        if (tid < D_) scat[tid] = x[((size_t)t * B_ + b) * D_ + tid];
        __syncthreads();   // S0

        if (isA) {
            // ---- q = x @ Wq + bq: full width, packed loads ----
            float q = 0.f;
            for (int c = 0; c < D_; c += 8) {
                const float4 w0 = tWq[(c >> 2) * D_ + gt];
                const float4 w1 = tWq[((c >> 2) + 1) * D_ + gt];
                q = fmaf(scat[c + 0], w0.x, q);
                q = fmaf(scat[c + 1], w0.y, q);
                q = fmaf(scat[c + 2], w0.z, q);
                q = fmaf(scat[c + 3], w0.w, q);
                q = fmaf(scat[c + 4], w1.x, q);
                q = fmaf(scat[c + 5], w1.y, q);
                q = fmaf(scat[c + 6], w1.z, q);
                q = fmaf(scat[c + 7], w1.w, q);
            }
            sQ[gt] = q + bqF;
            barA();
            // ---- Kvec: 8 warps, warp-per-row (already coalesced float4) ----
            const float4 q4lo = reinterpret_cast<const float4*>(sQ)[lane];
            const float4 q4hi = reinterpret_cast<const float4*>(sQ)[lane + 32];
            for (int r = wid; r < D_; r += 8) {
                const float* wr = Wk + (size_t)r * D_;
                const float4 wlo = reinterpret_cast<const float4*>(wr)[lane];
                const float4 whi = reinterpret_cast<const float4*>(wr)[lane + 32];
                float a = wlo.x * q4lo.x;
                a = fmaf(wlo.y, q4lo.y, a);
                a = fmaf(wlo.z, q4lo.z, a);
                a = fmaf(wlo.w, q4lo.w, a);
                a = fmaf(whi.x, q4hi.x, a);
                a = fmaf(whi.y, q4hi.y, a);
                a = fmaf(whi.z, q4hi.z, a);
                a = fmaf(whi.w, q4hi.w, a);
                #pragma unroll
                for (int off = 16; off; off >>= 1)
                    a += __shfl_xor_sync(0xffffffffu, a, off);
                if (lane == 0) sKv[r] = a;
            }
            barA();
            // ---- logit partials: thread = i-row ----
            {
                const float kv = sKv[gt];
                const float4* mr = reinterpret_cast<const float4*>(sM[gt]);
                const float4 m0 = mr[0], m1 = mr[1], m2 = mr[2], m3 = mr[3];
                const float mv[K_] = {m0.x,m0.y,m0.z,m0.w, m1.x,m1.y,m1.z,m1.w,
                                      m2.x,m2.y,m2.z,m2.w, m3.x,m3.y,m3.z,m3.w};
                float p[K_];
                #pragma unroll
                for (int j = 0; j < K_; ++j) p[j] = mv[j] * kv;
                #pragma unroll
                for (int off = 1; off < 32; off <<= 1) {
                    #pragma unroll
                    for (int j = 0; j < K_; ++j)
                        p[j] += __shfl_xor_sync(0xffffffffu, p[j], off);
                }
                if (lane == 0) {
                    #pragma unroll
                    for (int j = 0; j < K_; ++j) sLP[wid][j] = p[j];
                }
            }
            barA();
            if (tid < K_) {
                float l = 0.f;
                #pragma unroll
                for (int w = 0; w < 8; ++w) l += sLP[w][tid];
                l *= 0.0625f;
                float mx = l;
                #pragma unroll
                for (int off = 8; off; off >>= 1) mx = fmaxf(mx, __shfl_xor_sync(0xffffu, mx, off, 16));
                const float e = expf(l - mx);
                float s = e;
                #pragma unroll
                for (int off = 8; off; off >>= 1) s += __shfl_xor_sync(0xffffu, s, off, 16);
                const float a = e / s;
                sAttn[tid] = a;
                if (tid == 0) sNov = 1.f - 1.f / s;
                const float pr = MOMC * sPers[tid] + (1.f - MOMC) * a;
                sPers[tid] = pr;
                float el = -4.f * pr, em = el;
                #pragma unroll
                for (int off = 8; off; off >>= 1) em = fmaxf(em, __shfl_xor_sync(0xffffu, em, off, 16));
                const float ee = expf(el - em);
                float es = ee;
                #pragma unroll
                for (int off = 8; off; off >>= 1) es += __shfl_xor_sync(0xffffu, es, off, 16);
                sEvict[tid] = ee / es;
            }
            barA();
            {
                const float4* mr = reinterpret_cast<const float4*>(sM[gt]);
                const float4 m0 = mr[0], m1 = mr[1], m2 = mr[2], m3 = mr[3];
                const float mv[K_] = {m0.x,m0.y,m0.z,m0.w, m1.x,m1.y,m1.z,m1.w,
                                      m2.x,m2.y,m2.z,m2.w, m3.x,m3.y,m3.z,m3.w};
                float a = 0.f;
                #pragma unroll
                for (int j = 0; j < K_; ++j) a = fmaf(sAttn[j], mv[j], a);
                sMbar[gt] = a;
            }
            barA();
            // ---- r = m-bar @ Wv + bv: full width, packed loads ----
            float r = 0.f;
            for (int c = 0; c < D_; c += 8) {
                const float4 w0 = tWv[(c >> 2) * D_ + gt];
                const float4 w1 = tWv[((c >> 2) + 1) * D_ + gt];
                r = fmaf(sMbar[c + 0], w0.x, r);
                r = fmaf(sMbar[c + 1], w0.y, r);
                r = fmaf(sMbar[c + 2], w0.z, r);
                r = fmaf(sMbar[c + 3], w0.w, r);
                r = fmaf(sMbar[c + 4], w1.x, r);
                r = fmaf(sMbar[c + 5], w1.y, r);
                r = fmaf(sMbar[c + 6], w1.z, r);
                r = fmaf(sMbar[c + 7], w1.w, r);
            }
            scat[D_ + gt] = r + bvF;
        } else {
            // ============ GROUP B: uninterrupted eg/wc GEMM, packed loads ============
            float acc[K_];
            float aux = 0.f;
            #pragma unroll
            for (int j = 0; j < K_; ++j) acc[j] = 0.f;
            for (int c = 0; c < D_; c += 4) {
                const float4 wx = TmX[(c >> 2) * D_ + og];
                const float4 ws = TmS[(c >> 2) * D_ + og];
                const float wav[4] = {wx.x, wx.y, wx.z, wx.w};
                const float wsv[4] = {ws.x, ws.y, ws.z, ws.w};
                #pragma unroll
                for (int u = 0; u < 4; ++u) {
                    const int i = c + u;
                    aux = fmaf(scat[i], wav[u], aux);
                    const float4* mr = reinterpret_cast<const float4*>(sM[i]);
                    const float4 m0 = mr[0], m1 = mr[1], m2 = mr[2], m3 = mr[3];
                    const float mv[K_] = {m0.x,m0.y,m0.z,m0.w, m1.x,m1.y,m1.z,m1.w,
                                          m2.x,m2.y,m2.z,m2.w, m3.x,m3.y,m3.z,m3.w};
                    #pragma unroll
                    for (int j = 0; j < K_; ++j)
                        acc[j] = fmaf(mv[j], wsv[u], acc[j]);
                }
            }
            if (hb == 0) {   // erase epilogue (warps 8-11)
                float e[K_];
                #pragma unroll
                for (int j = 0; j < K_; ++j) e[j] = sigmf(acc[j] + aux + cbM);
                float4* er = reinterpret_cast<float4*>(sE[o]);
                er[0] = make_float4(e[0],  e[1],  e[2],  e[3]);
                er[1] = make_float4(e[4],  e[5],  e[6],  e[7]);
                er[2] = make_float4(e[8],  e[9],  e[10], e[11]);
                er[3] = make_float4(e[12], e[13], e[14], e[15]);
            } else {         // write-candidate epilogue + gstats (warps 12-15)
                float g[K_], gs[K_], gq[K_];
                #pragma unroll
                for (int j = 0; j < K_; ++j) {
                    g[j]  = geluf(acc[j] + aux + cbM);
                    gs[j] = g[j];
                    gq[j] = g[j] * g[j];
                }
                #pragma unroll
                for (int off = 1; off < 32; off <<= 1) {
                    #pragma unroll
                    for (int j = 0; j < K_; ++j) {
                        gs[j] += __shfl_xor_sync(0xffffffffu, gs[j], off);
                        gq[j] += __shfl_xor_sync(0xffffffffu, gq[j], off);
                    }
                }
                if (lane == 0) {
                    #pragma unroll
                    for (int j = 0; j < K_; ++j) {
                        sGP[wid - 12][j]      = gs[j];
                        sGP[wid - 12][K_ + j] = gq[j];
                    }
                }
                float4* gr = reinterpret_cast<float4*>(sG[o]);
                gr[0] = make_float4(g[0],  g[1],  g[2],  g[3]);
                gr[1] = make_float4(g[4],  g[5],  g[6],  g[7]);
                gr[2] = make_float4(g[8],  g[9],  g[10], g[11]);
                gr[3] = make_float4(g[12], g[13], g[14], g[15]);
            }
        }
        __syncthreads();   // S1: r + sG/sE/sGP ready; A done reading sM

        // ---- fu / wg1 quadrants: A = cat[0..255], B = cat[256..511], packed ----
        float accf = 0.f;
        {
            const int base = isA ? 0 : 256;
            for (int c = 0; c < 256; c += 8) {
                const int cc = base + c;
                const float4 w0 = Tf[(cc >> 2) * D_ + og];
                const float4 w1 = Tf[((cc >> 2) + 1) * D_ + og];
                accf = fmaf(scat[cc + 0], w0.x, accf);
                accf = fmaf(scat[cc + 1], w0.y, accf);
                accf = fmaf(scat[cc + 2], w0.z, accf);
                accf = fmaf(scat[cc + 3], w0.w, accf);
                accf = fmaf(scat[cc + 4], w1.x, accf);
                accf = fmaf(scat[cc + 5], w1.y, accf);
                accf = fmaf(scat[cc + 6], w1.z, accf);
                accf = fmaf(scat[cc + 7], w1.w, accf);
            }
        }
        if (!isA) { if (hb == 0) sFBf[o] = accf; else sFBg[o] = accf; }
        __syncthreads();   // S2

        float hf = 0.f;
        if (isA) {
            if (hb == 0) {
                hf = geluf(accf + sFBf[o] + cA2);
                float b0 = hf, b1 = hf * hf;
                #pragma unroll
                for (int off = 1; off < 32; off <<= 1) {
                    b0 += __shfl_xor_sync(0xffffffffu, b0, off);
                    b1 += __shfl_xor_sync(0xffffffffu, b1, off);
                }
                if (lane == 0) { sBRf[wid][0] = b0; sBRf[wid][1] = b1; }
            } else {
                const float hg = geluf(accf + sFBg[o] + cA2);
                float a2 = hg * cA3;
                #pragma unroll
                for (int off = 1; off < 32; off <<= 1)
                    a2 += __shfl_xor_sync(0xffffffffu, a2, off);
                if (lane == 0) sBRg[wid - 4] = a2;
            }
            barA();
            if (tid < 3) {
                float s;
                if (tid < 2) s = sBRf[0][tid] + sBRf[1][tid] + sBRf[2][tid] + sBRf[3][tid];
                else         s = sBRg[0] + sBRg[1] + sBRg[2] + sBRg[3];
                sF[tid] = s;
                st_peer_f32(peer_addr(smem_u32(&eF[tid]), peer), s);
            }
        } else if (gt < 2 * K_) {
            const float s = sGP[0][gt] + sGP[1][gt] + sGP[2][gt] + sGP[3][gt];
            sGloc[gt] = s;
            st_peer_f32(peer_addr(smem_u32(&eG[gt]), peer), s);
        }
        cluster_sync_();   // C1: eF + eG exchanged

        const float gw = sigmf(sF[2] + eF[2] + wg2b0) * sNov;
        if (tid < K_) {
            sPers[tid] += sEvict[tid] * gw * 0.1f;
            const float gsum = sGloc[tid] + eG[tid];
            const float gsq  = sGloc[K_ + tid] + eG[K_ + tid];
            const float mean = gsum * (1.f / D_);
            const float var  = gsq * (1.f / D_) - mean * mean;
            sMean[tid] = mean;
            sRstd[tid] = rsqrtf(var + EPSLN);
        }
        __syncthreads();   // S3: mean/rstd visible

        float uu = 0.f;
        if (isA) {
            if (hb == 0) {
                const float fsum = sF[0] + eF[0], fsq = sF[1] + eF[1];
                const float fmn = fsum * (1.f / D_);
                const float fvr = fsq * (1.f / D_) - fmn * fmn;
                const float frs = rsqrtf(fvr + EPSLN);
                const float outt = (hf - fmn) * frs * cA3 + cA4;
                uu = outt + scat[og];
                float b0 = uu, b1 = uu * uu;
                #pragma unroll
                for (int off = 1; off < 32; off <<= 1) {
                    b0 += __shfl_xor_sync(0xffffffffu, b0, off);
                    b1 += __shfl_xor_sync(0xffffffffu, b1, off);
                }
                if (lane == 0) { sUW[wid][0] = b0; sUW[wid][1] = b1; }
            }
            barA();
            if (tid < 2) {
                const float s = sUW[0][tid] + sUW[1][tid] + sUW[2][tid] + sUW[3][tid];
                sU[tid] = s;
                st_peer_f32(peer_addr(smem_u32(&eU[tid]), peer), s);
            }
        } else {
            const int colb = (gt & 1) * 8;
            float nm[8];
            #pragma unroll
            for (int c = 0; c < 8; ++c) {
                const int j = colb + c;
                const float al = gw * sEvict[j];
                const float wr = (sG[urow][j] - sMean[j]) * sRstd[j] * cgU + cbU;
                nm[c] = sM[grow][j] * (1.f - al * sE[urow][j]) + al * wr;
            }
            float4* rowp = reinterpret_cast<float4*>(&sM[grow][colb]);
            rowp[0] = make_float4(nm[0], nm[1], nm[2], nm[3]);
            rowp[1] = make_float4(nm[4], nm[5], nm[6], nm[7]);
            uint32_t ra = peer_addr(smem_u32(&sM[grow][colb]), peer);
            st_peer_f128(ra,      make_float4(nm[0], nm[1], nm[2], nm[3]));
            st_peer_f128(ra + 16, make_float4(nm[4], nm[5], nm[6], nm[7]));
        }
        cluster_sync_();   // C2: eU + peer M halves visible

        if (isA && hb == 0) {
            const float usum = sU[0] + eU[0], usq = sU[1] + eU[1];
            const float um = usum * (1.f / D_);
            const float uv = usq * (1.f / D_) - um * um;
            const float rr = rsqrtf(uv + EPSLN);
            out[((size_t)t * B_ + b) * D_ + og] = (uu - um) * rr * ongo + onbo;
        }
    }

    // proto = transpose(M, (1,0,2)) : [K, B, d]
    if (isA && hb == 0) {
        #pragma unroll
        for (int j = 0; j < K_; ++j)
            out[(size_t)S_ * B_ * D_ + ((size_t)j * B_ + b) * D_ + og] = sM[og][j];
    }
}

extern "C" void kernel_launch(void* const* d_in, const int* in_sizes, int n_in,
                              void* d_out, int out_size) {
    (void)in_sizes; (void)n_in; (void)out_size;
    const float* Wq   = (const float*)d_in[2];
    const float* Wk   = (const float*)d_in[4];
    const float* Wv   = (const float*)d_in[6];
    const float* wg1W = (const float*)d_in[8];
    const float* egW  = (const float*)d_in[12];
    const float* wcW  = (const float*)d_in[14];
    const float* fuW  = (const float*)d_in[18];

    float4 *pEgX, *pEgS, *pWcX, *pWcS, *pFu, *pWg1, *pWq, *pWv;
    cudaGetSymbolAddress((void**)&pEgX, tEgX);
    cudaGetSymbolAddress((void**)&pEgS, tEgS);
    cudaGetSymbolAddress((void**)&pWcX, tWcX);
    cudaGetSymbolAddress((void**)&pWcS, tWcS);
    cudaGetSymbolAddress((void**)&pFu,  tFu);
    cudaGetSymbolAddress((void**)&pWg1, tWg1);
    cudaGetSymbolAddress((void**)&pWq,  tWq);
    cudaGetSymbolAddress((void**)&pWv,  tWv);

    pack_kernel<<<64, 256>>>(egW,            pEgX);
    pack_kernel<<<64, 256>>>(egW + 256*256,  pEgS);
    pack_kernel<<<64, 256>>>(wcW,            pWcX);
    pack_kernel<<<64, 256>>>(wcW + 256*256,  pWcS);
    pack_kernel<<<128, 256>>>(fuW,           pFu);
    pack_kernel<<<128, 256>>>(wg1W,          pWg1);
    pack_kernel<<<64, 256>>>(Wq,             pWq);
    pack_kernel<<<64, 256>>>(Wv,             pWv);

    memunit_kernel<<<2 * B_, NT>>>(
        (const float*)d_in[0],  (const float*)d_in[1],
        Wk,                     (const float*)d_in[3],
        (const float*)d_in[7],
        (const float*)d_in[9],  (const float*)d_in[10],
        (const float*)d_in[11],
        (const float*)d_in[13], (const float*)d_in[15],
        (const float*)d_in[16], (const float*)d_in[17],
        (const float*)d_in[19],
        (const float*)d_in[20], (const float*)d_in[21],
        (const float*)d_in[22], (const float*)d_in[23],
        (float*)d_out);
}